// round 14
// baseline (speedup 1.0000x reference)
#include <cuda_runtime.h>
#include <cuda_bf16.h>
#include <math.h>

// Rotated-ROI-align, replicating the JAX f32 reference op-for-op.
// Output: [32 rois][32 y][32 x] f32, 32768 elements. Bit-exact (rel_err 0.0
// measured R4/R6/R8/R9/R10).
//
// FINAL CONFIGURATION = R10 measured best (6.272 us ncu, 6.62 us harness):
//   grid 256 = (32 rois, 8), block (32, 4); warp 0 computes per-ROI affine
//   constants with a custom short-range double sincos, broadcast via smem.
//
// Measured history (ncu dur):
//   R4  6.528  lib sincos + warp0/smem broadcast, 128x(32,8)
//   R6  6.432  custom Cody-Waite sincos + broadcast, 128x(32,8)
//   R8  7.072  no broadcast, per-thread constants   <- regression, reverted
//   R9  6.496  revert to R6 config, confirmed
//   R10 6.272  geometry 256x(32,4)                  <- best, FINAL
//   R11-13     512x(32,2) probe never measured (broker timeouts); parked.
// Kernel is launch/ramp-overhead bound: all pipes <=2.7% of peak, DRAM 0.4%
// (gathers are L2-resident), issue ~6%. Body-level optimization exhausted.
//
// Correctness-critical details (verified by measurement):
//  - __fmul_rn/__fadd_rn forbid FMA contraction (JAX emits separate mul/add).
//  - rintf == jnp.round (round-half-to-even).
//  - JAX advanced indexing: negative indices WRAP (+256), THEN clamp [0,255].
//  - feature values truncated toward zero: (float)(int)v == astype(int32).
//  - meshgrid 'xy': out[roi][i][j] uses y=i, x=j; row0[a,b] -> a*256+b.
//  - sincos must be double-accurate (f32 sin/cos flips round() decisions);
//    short Cody-Waite double path, error ~1e-15, measured bit-exact.

#define NUMROI 32
#define PH 32
#define PW 32
#define FDIM 256
#define PI_F 3.1415927f   // float32(3.1415926535) = 0x40490FDB

__device__ __forceinline__ float fm(float a, float b) { return __fmul_rn(a, b); }
__device__ __forceinline__ float fa(float a, float b) { return __fadd_rn(a, b); }

// JAX gather index semantics: wrap negatives once, then clip.
__device__ __forceinline__ int wrap_clamp(int v) {
    if (v < 0) v += FDIM;
    return min(max(v, 0), FDIM - 1);
}

// Double-precision sincos for x in [0, ~566]. Error ~1e-15 absolute.
// 2-word Cody-Waite reduction (k <= 360) + fdlibm kernel polynomials.
__device__ __forceinline__ void sincos_short(float xf, float* s_out, float* c_out)
{
    const double x = (double)xf;
    const double TWO_OVER_PI = 6.36619772367581382433e-01;
    const double PIO2_HI     = 1.57079632679489655800e+00;  // pi/2 (double)
    const double PIO2_LO     = 6.12323399573676603587e-17;  // pi/2 - PIO2_HI

    const int    k  = __double2int_rn(x * TWO_OVER_PI);     // 0..360
    const double kd = (double)k;
    double r = __fma_rn(-kd, PIO2_HI, x);                   // exact-ish cancel
    r        = __fma_rn(-kd, PIO2_LO, r);                   // |r| <= pi/4 + eps
    const double z = r * r;

    // sin(r) = r + z*r*poly_s(z)     (fdlibm __kernel_sin S1..S6)
    double sp = __fma_rn(z,  1.58969099521155010221e-10, -2.50507602534068634195e-08);
    sp = __fma_rn(z, sp,  2.75573137070700676789e-06);
    sp = __fma_rn(z, sp, -1.98412698298579493134e-04);
    sp = __fma_rn(z, sp,  8.33333333332248946124e-03);
    sp = __fma_rn(z, sp, -1.66666666666666324348e-01);
    const double sr = __fma_rn(z * r, sp, r);

    // cos(r) = 1 - z/2 + z^2*poly_c(z)  (fdlibm __kernel_cos C1..C6)
    double cp = __fma_rn(z, -1.13596475577881948265e-11,  2.08757232129817482790e-09);
    cp = __fma_rn(z, cp, -2.75573143513906633035e-07);
    cp = __fma_rn(z, cp,  2.48015872894767294178e-05);
    cp = __fma_rn(z, cp, -1.38888888888741095749e-03);
    cp = __fma_rn(z, cp,  4.16666666666666019037e-02);
    const double cr = __fma_rn(z * z, cp, 1.0 - 0.5 * z);

    // Quadrant fixup: q = k mod 4 (k >= 0 here).
    const int q = k & 3;
    double s_d = (q & 1) ? cr : sr;
    double c_d = (q & 1) ? sr : cr;
    if (q == 2 || q == 3) s_d = -s_d;   // sin sign
    if (q == 1 || q == 2) c_d = -c_d;   // cos sign

    *s_out = (float)s_d;
    *c_out = (float)c_d;
}

__global__ __launch_bounds__(128)
void rroi_align_kernel(const float* __restrict__ features,
                       const float* __restrict__ rois,
                       float* __restrict__ out)
{
    __shared__ float sM[6];   // M00, M01, M02, M10, M11, M12

    const int roi = blockIdx.x;                       // 0..31
    const int j   = threadIdx.x;                      // x index, 0..31
    const int i   = threadIdx.y + blockIdx.y * 4;     // y index, 0..31

    if (threadIdx.y == 0) {   // warp 0 computes the per-ROI affine constants
        // roi_idx = [0] + range(31)
        const int src = (roi == 0) ? 0 : (roi - 1);
        const float r1 = __ldg(&rois[src * 6 + 1]);
        const float r2 = __ldg(&rois[src * 6 + 2]);
        const float r3 = __ldg(&rois[src * 6 + 3]);
        const float r4 = __ldg(&rois[src * 6 + 4]);
        const float r5 = __ldg(&rois[src * 6 + 5]);

        const float ss = 1.0f;

        // M5 = (r5 * 180.0) * PI  (two f32 multiplies, left-assoc)
        const float M5 = fm(fm(r5, 180.0f), PI_F);

        // roi_pw = (M4/M3) * pw
        const float roi_pw = fm(__fdiv_rn(r4, r3), (float)PW);
        const float dx = -__fdiv_rn(roi_pw, 2.0f);
        const float dy = -((float)PH) / 2.0f;             // -16, exact
        const float Sx = fm(__fdiv_rn(r4, roi_pw), ss);
        const float Sy = __fdiv_rn(r3, (float)PH * ss);   // r3 / 32

        float Alpha, Beta;
        sincos_short(M5, &Beta, &Alpha);                  // sin -> Beta, cos -> Alpha
        const float Dx = fm(r1, ss);
        const float Dy = fm(r2, ss);

        const float M00 = fm(Alpha, Sx);
        const float M01 = fm(Beta,  Sy);
        const float M02 = fa(fa(fm(M00, dx), fm(M01, dy)), Dx);
        const float M10 = fm(-Beta, Sx);
        const float M11 = fm(Alpha, Sy);
        const float M12 = fa(fa(fm(M10, dx), fm(M11, dy)), Dy);

        if (threadIdx.x == 0) {
            sM[0] = M00; sM[1] = M01; sM[2] = M02;
            sM[3] = M10; sM[4] = M11; sM[5] = M12;
        }
    }
    __syncthreads();

    const float M00 = sM[0], M01 = sM[1], M02 = sM[2];
    const float M10 = sM[3], M11 = sM[4], M12 = sM[5];

    const float x  = (float)j;
    const float y  = (float)i;
    const float x1 = x + 1.0f;   // exact
    const float y1 = y + 1.0f;   // exact

    // P = M0*x + M1*y + M2, evaluated as ((mul)+(mul))+add, no FMA
    const float P0 = fa(fa(fm(M00, x ), fm(M01, y )), M02);
    const float P1 = fa(fa(fm(M10, x ), fm(M11, y )), M12);
    const float P2 = fa(fa(fm(M00, x ), fm(M01, y1)), M02);
    const float P3 = fa(fa(fm(M10, x ), fm(M11, y1)), M12);
    const float P4 = fa(fa(fm(M00, x1), fm(M01, y )), M02);
    const float P5 = fa(fa(fm(M10, x1), fm(M11, y )), M12);
    const float P6 = fa(fa(fm(M00, x1), fm(M01, y1)), M02);
    const float P7 = fa(fa(fm(M10, x1), fm(M11, y1)), M12);

    const float W1 = (float)(FDIM - 1);

    // rintf == round-half-to-even == jnp.round
    const float leftMost   = fmaxf(rintf(fminf(fminf(P0, P2), fminf(P4, P6))), 0.0f);
    const float rightMost  = fminf(rintf(fmaxf(fmaxf(P0, P2), fmaxf(P4, P6))), W1);
    const float topMost    = fmaxf(rintf(fminf(fminf(P1, P3), fminf(P5, P7))), 0.0f);
    const float bottomMost = fminf(rintf(fmaxf(fmaxf(P1, P3), fmaxf(P5, P7))), W1);

    const float bin_cx = fm(fa(leftMost, rightMost), 0.5f);   // /2.0 == *0.5
    const float bin_cy = fm(fa(topMost, bottomMost), 0.5f);

    const float fx = floorf(bin_cx);
    const float fy = floorf(bin_cy);

    // JAX index semantics: wrap negatives by +256, then clamp to [0,255]
    const int il = wrap_clamp((int)fx);
    const int ir = wrap_clamp((int)ceilf(bin_cx));
    const int it = wrap_clamp((int)fy);
    const int ib = wrap_clamp((int)ceilf(bin_cy));

    const float rx = fa(bin_cx, -fx);   // exact fractional part
    const float ry = fa(bin_cy, -fy);

    const float wlt = fm(1.0f - rx, 1.0f - ry);
    const float wrt = fm(rx,        1.0f - ry);
    const float wrb = fm(rx,        ry);
    const float wlb = fm(1.0f - rx, ry);

    // row0 = features[0,0]: flat index a*256 + b, then trunc-toward-zero to int
    const float lt = (float)(int)__ldg(&features[il * FDIM + it]);
    const float rt = (float)(int)__ldg(&features[ir * FDIM + it]);
    const float lb = (float)(int)__ldg(&features[il * FDIM + ib]);
    const float rb = (float)(int)__ldg(&features[ir * FDIM + ib]);

    const float result = fa(fa(fa(fm(lt, wlt), fm(rt, wrt)), fm(rb, wrb)), fm(lb, wlb));

    out[(roi * PH + i) * PW + j] = result;
}

extern "C" void kernel_launch(void* const* d_in, const int* in_sizes, int n_in,
                              void* d_out, int out_size)
{
    // Locate features (256^3 elements) and rois (32*6 = 192) by size;
    // fall back to positional (d_in[3], d_in[4]) if sizes are ambiguous.
    const float* features = nullptr;
    const float* rois     = nullptr;
    for (int k = 0; k < n_in; k++) {
        if (in_sizes[k] == 256 * 256 * 256) features = (const float*)d_in[k];
        else if (in_sizes[k] == 192)        rois     = (const float*)d_in[k];
    }
    if (!features && n_in > 3) features = (const float*)d_in[3];
    if (!rois && n_in > 4)     rois     = (const float*)d_in[4];

    dim3 block(32, 4);
    dim3 grid(NUMROI, 8);
    rroi_align_kernel<<<grid, block>>>(features, rois, (float*)d_out);
}

// round 16
// speedup vs baseline: 1.2124x; 1.2124x over previous
#include <cuda_runtime.h>
#include <cuda_bf16.h>
#include <math.h>

// Rotated-ROI-align, replicating the JAX f32 reference op-for-op.
// Output: [32 rois][32 y][32 x] f32, 32768 elements. Bit-exact (rel_err 0.0
// on every measured run: R4/R6/R8/R9/R10/R14).
//
// FINAL CONFIGURATION = measured best, confirmed twice:
//   R10 6.272 us ncu / R14 6.304 us ncu
//   grid 256 = (32 rois, 8), block (32, 4); warp 0 computes per-ROI affine
//   constants with a custom short-range double sincos, broadcast via smem.
//
// Measured history (ncu dur):
//   R4  6.528  lib sincos + warp0/smem broadcast, 128x(32,8)
//   R6  6.432  custom Cody-Waite sincos + broadcast, 128x(32,8)
//   R8  7.072  no broadcast, per-thread constants   <- regression, reverted
//   R9  6.496  revert confirmed
//   R10 6.272  geometry 256x(32,4)                  <- best
//   R14 6.304  reproduction                         <- baseline confirmed 2x
//   512x(32,2) probe: 5 broker timeouts, never measured; permanently parked.
// Kernel is launch/ramp-overhead bound: all pipes <=2.7% of peak, DRAM 0.4%
// (gathers are L2-resident), issue ~6%. Optimization space exhausted.
//
// Correctness-critical details (verified by measurement):
//  - __fmul_rn/__fadd_rn forbid FMA contraction (JAX emits separate mul/add).
//  - rintf == jnp.round (round-half-to-even).
//  - JAX advanced indexing: negative indices WRAP (+256), THEN clamp [0,255].
//  - feature values truncated toward zero: (float)(int)v == astype(int32).
//  - meshgrid 'xy': out[roi][i][j] uses y=i, x=j; row0[a,b] -> a*256+b.
//  - sincos must be double-accurate (f32 sin/cos flips round() decisions);
//    short Cody-Waite double path, error ~1e-15, measured bit-exact.

#define NUMROI 32
#define PH 32
#define PW 32
#define FDIM 256
#define PI_F 3.1415927f   // float32(3.1415926535) = 0x40490FDB

__device__ __forceinline__ float fm(float a, float b) { return __fmul_rn(a, b); }
__device__ __forceinline__ float fa(float a, float b) { return __fadd_rn(a, b); }

// JAX gather index semantics: wrap negatives once, then clip.
__device__ __forceinline__ int wrap_clamp(int v) {
    if (v < 0) v += FDIM;
    return min(max(v, 0), FDIM - 1);
}

// Double-precision sincos for x in [0, ~566]. Error ~1e-15 absolute.
// 2-word Cody-Waite reduction (k <= 360) + fdlibm kernel polynomials.
__device__ __forceinline__ void sincos_short(float xf, float* s_out, float* c_out)
{
    const double x = (double)xf;
    const double TWO_OVER_PI = 6.36619772367581382433e-01;
    const double PIO2_HI     = 1.57079632679489655800e+00;  // pi/2 (double)
    const double PIO2_LO     = 6.12323399573676603587e-17;  // pi/2 - PIO2_HI

    const int    k  = __double2int_rn(x * TWO_OVER_PI);     // 0..360
    const double kd = (double)k;
    double r = __fma_rn(-kd, PIO2_HI, x);                   // exact-ish cancel
    r        = __fma_rn(-kd, PIO2_LO, r);                   // |r| <= pi/4 + eps
    const double z = r * r;

    // sin(r) = r + z*r*poly_s(z)     (fdlibm __kernel_sin S1..S6)
    double sp = __fma_rn(z,  1.58969099521155010221e-10, -2.50507602534068634195e-08);
    sp = __fma_rn(z, sp,  2.75573137070700676789e-06);
    sp = __fma_rn(z, sp, -1.98412698298579493134e-04);
    sp = __fma_rn(z, sp,  8.33333333332248946124e-03);
    sp = __fma_rn(z, sp, -1.66666666666666324348e-01);
    const double sr = __fma_rn(z * r, sp, r);

    // cos(r) = 1 - z/2 + z^2*poly_c(z)  (fdlibm __kernel_cos C1..C6)
    double cp = __fma_rn(z, -1.13596475577881948265e-11,  2.08757232129817482790e-09);
    cp = __fma_rn(z, cp, -2.75573143513906633035e-07);
    cp = __fma_rn(z, cp,  2.48015872894767294178e-05);
    cp = __fma_rn(z, cp, -1.38888888888741095749e-03);
    cp = __fma_rn(z, cp,  4.16666666666666019037e-02);
    const double cr = __fma_rn(z * z, cp, 1.0 - 0.5 * z);

    // Quadrant fixup: q = k mod 4 (k >= 0 here).
    const int q = k & 3;
    double s_d = (q & 1) ? cr : sr;
    double c_d = (q & 1) ? sr : cr;
    if (q == 2 || q == 3) s_d = -s_d;   // sin sign
    if (q == 1 || q == 2) c_d = -c_d;   // cos sign

    *s_out = (float)s_d;
    *c_out = (float)c_d;
}

__global__ __launch_bounds__(128)
void rroi_align_kernel(const float* __restrict__ features,
                       const float* __restrict__ rois,
                       float* __restrict__ out)
{
    __shared__ float sM[6];   // M00, M01, M02, M10, M11, M12

    const int roi = blockIdx.x;                       // 0..31
    const int j   = threadIdx.x;                      // x index, 0..31
    const int i   = threadIdx.y + blockIdx.y * 4;     // y index, 0..31

    if (threadIdx.y == 0) {   // warp 0 computes the per-ROI affine constants
        // roi_idx = [0] + range(31)
        const int src = (roi == 0) ? 0 : (roi - 1);
        const float r1 = __ldg(&rois[src * 6 + 1]);
        const float r2 = __ldg(&rois[src * 6 + 2]);
        const float r3 = __ldg(&rois[src * 6 + 3]);
        const float r4 = __ldg(&rois[src * 6 + 4]);
        const float r5 = __ldg(&rois[src * 6 + 5]);

        const float ss = 1.0f;

        // M5 = (r5 * 180.0) * PI  (two f32 multiplies, left-assoc)
        const float M5 = fm(fm(r5, 180.0f), PI_F);

        // roi_pw = (M4/M3) * pw
        const float roi_pw = fm(__fdiv_rn(r4, r3), (float)PW);
        const float dx = -__fdiv_rn(roi_pw, 2.0f);
        const float dy = -((float)PH) / 2.0f;             // -16, exact
        const float Sx = fm(__fdiv_rn(r4, roi_pw), ss);
        const float Sy = __fdiv_rn(r3, (float)PH * ss);   // r3 / 32

        float Alpha, Beta;
        sincos_short(M5, &Beta, &Alpha);                  // sin -> Beta, cos -> Alpha
        const float Dx = fm(r1, ss);
        const float Dy = fm(r2, ss);

        const float M00 = fm(Alpha, Sx);
        const float M01 = fm(Beta,  Sy);
        const float M02 = fa(fa(fm(M00, dx), fm(M01, dy)), Dx);
        const float M10 = fm(-Beta, Sx);
        const float M11 = fm(Alpha, Sy);
        const float M12 = fa(fa(fm(M10, dx), fm(M11, dy)), Dy);

        if (threadIdx.x == 0) {
            sM[0] = M00; sM[1] = M01; sM[2] = M02;
            sM[3] = M10; sM[4] = M11; sM[5] = M12;
        }
    }
    __syncthreads();

    const float M00 = sM[0], M01 = sM[1], M02 = sM[2];
    const float M10 = sM[3], M11 = sM[4], M12 = sM[5];

    const float x  = (float)j;
    const float y  = (float)i;
    const float x1 = x + 1.0f;   // exact
    const float y1 = y + 1.0f;   // exact

    // P = M0*x + M1*y + M2, evaluated as ((mul)+(mul))+add, no FMA
    const float P0 = fa(fa(fm(M00, x ), fm(M01, y )), M02);
    const float P1 = fa(fa(fm(M10, x ), fm(M11, y )), M12);
    const float P2 = fa(fa(fm(M00, x ), fm(M01, y1)), M02);
    const float P3 = fa(fa(fm(M10, x ), fm(M11, y1)), M12);
    const float P4 = fa(fa(fm(M00, x1), fm(M01, y )), M02);
    const float P5 = fa(fa(fm(M10, x1), fm(M11, y )), M12);
    const float P6 = fa(fa(fm(M00, x1), fm(M01, y1)), M02);
    const float P7 = fa(fa(fm(M10, x1), fm(M11, y1)), M12);

    const float W1 = (float)(FDIM - 1);

    // rintf == round-half-to-even == jnp.round
    const float leftMost   = fmaxf(rintf(fminf(fminf(P0, P2), fminf(P4, P6))), 0.0f);
    const float rightMost  = fminf(rintf(fmaxf(fmaxf(P0, P2), fmaxf(P4, P6))), W1);
    const float topMost    = fmaxf(rintf(fminf(fminf(P1, P3), fminf(P5, P7))), 0.0f);
    const float bottomMost = fminf(rintf(fmaxf(fmaxf(P1, P3), fmaxf(P5, P7))), W1);

    const float bin_cx = fm(fa(leftMost, rightMost), 0.5f);   // /2.0 == *0.5
    const float bin_cy = fm(fa(topMost, bottomMost), 0.5f);

    const float fx = floorf(bin_cx);
    const float fy = floorf(bin_cy);

    // JAX index semantics: wrap negatives by +256, then clamp to [0,255]
    const int il = wrap_clamp((int)fx);
    const int ir = wrap_clamp((int)ceilf(bin_cx));
    const int it = wrap_clamp((int)fy);
    const int ib = wrap_clamp((int)ceilf(bin_cy));

    const float rx = fa(bin_cx, -fx);   // exact fractional part
    const float ry = fa(bin_cy, -fy);

    const float wlt = fm(1.0f - rx, 1.0f - ry);
    const float wrt = fm(rx,        1.0f - ry);
    const float wrb = fm(rx,        ry);
    const float wlb = fm(1.0f - rx, ry);

    // row0 = features[0,0]: flat index a*256 + b, then trunc-toward-zero to int
    const float lt = (float)(int)__ldg(&features[il * FDIM + it]);
    const float rt = (float)(int)__ldg(&features[ir * FDIM + it]);
    const float lb = (float)(int)__ldg(&features[il * FDIM + ib]);
    const float rb = (float)(int)__ldg(&features[ir * FDIM + ib]);

    const float result = fa(fa(fa(fm(lt, wlt), fm(rt, wrt)), fm(rb, wrb)), fm(lb, wlb));

    out[(roi * PH + i) * PW + j] = result;
}

extern "C" void kernel_launch(void* const* d_in, const int* in_sizes, int n_in,
                              void* d_out, int out_size)
{
    // Locate features (256^3 elements) and rois (32*6 = 192) by size;
    // fall back to positional (d_in[3], d_in[4]) if sizes are ambiguous.
    const float* features = nullptr;
    const float* rois     = nullptr;
    for (int k = 0; k < n_in; k++) {
        if (in_sizes[k] == 256 * 256 * 256) features = (const float*)d_in[k];
        else if (in_sizes[k] == 192)        rois     = (const float*)d_in[k];
    }
    if (!features && n_in > 3) features = (const float*)d_in[3];
    if (!rois && n_in > 4)     rois     = (const float*)d_in[4];

    dim3 block(32, 4);
    dim3 grid(NUMROI, 8);
    rroi_align_kernel<<<grid, block>>>(features, rois, (float*)d_out);
}